// round 5
// baseline (speedup 1.0000x reference)
#include <cuda_runtime.h>
#include <cuda_bf16.h>
#include <math.h>

// ---------------------------------------------------------------------------
// Llama-style decode step, BATCH=8, S=1. HBM-bound GEMVs (f32x2 FMA, 8 cols
// per thread, X staged once, barrier-free unroll-8 stream loop) +
// flash-decode attention.
// ---------------------------------------------------------------------------

#define DM 4096
#define NH 32
#define NKV 8
#define HD 128
#define HID 14336
#define VOC 32000
#define MSEQ 2048
#define B8 8
#define ACH 128
#define NCHK 16

// ------------------------- scratch (device globals) -------------------------
__device__ float g_h[B8 * DM];
__device__ float g_xn[B8 * DM];
__device__ float g_xq[B8 * NH * HD];
__device__ float g_xk[B8 * NKV * HD];
__device__ float g_xv[B8 * NKV * HD];
__device__ float g_pm[B8 * NH * NCHK];
__device__ float g_pl[B8 * NH * NCHK];
__device__ float g_po[B8 * NH * NCHK * HD];
__device__ float g_attn[B8 * DM];
__device__ float g_g[B8 * HID];
__device__ float g_PA[128 * 8 * 4096];   // 4,194,304 floats
__device__ float g_PB[128 * 8 * 4096];   // 4,194,304 floats

// ------------------------- helpers -------------------------
__device__ __forceinline__ void fma4(float4& a, float s, const float4& w) {
    a.x = fmaf(s, w.x, a.x);
    a.y = fmaf(s, w.y, a.y);
    a.z = fmaf(s, w.z, a.z);
    a.w = fmaf(s, w.w, a.w);
}

__device__ __forceinline__ unsigned long long dup_f32(float v) {
    unsigned long long pv;
    asm("mov.b64 %0, {%1, %1};" : "=l"(pv) : "f"(v));
    return pv;
}

// ---- GEMM inner step: 2 LDG.128 + 4 broadcast LDS.128 + 32 FFMA2 per k ----
#define GEMM_KSTEP8(wp, stride)                                                \
    {                                                                          \
        ulonglong2 wA = __ldg((const ulonglong2*)(wp));                        \
        ulonglong2 wB = __ldg((const ulonglong2*)((wp) + 4));                  \
        (wp) += (stride);                                                      \
        _Pragma("unroll") for (int p = 0; p < 4; ++p) {                        \
            ulonglong2 xp = *(const ulonglong2*)&xs[kk][2 * p];                \
            asm("fma.rn.f32x2 %0, %8, %10, %0;\n\t"                            \
                "fma.rn.f32x2 %1, %8, %11, %1;\n\t"                            \
                "fma.rn.f32x2 %2, %8, %12, %2;\n\t"                            \
                "fma.rn.f32x2 %3, %8, %13, %3;\n\t"                            \
                "fma.rn.f32x2 %4, %9, %10, %4;\n\t"                            \
                "fma.rn.f32x2 %5, %9, %11, %5;\n\t"                            \
                "fma.rn.f32x2 %6, %9, %12, %6;\n\t"                            \
                "fma.rn.f32x2 %7, %9, %13, %7;"                                \
                : "+l"(aA01[2 * p]), "+l"(aA23[2 * p]),                        \
                  "+l"(aB01[2 * p]), "+l"(aB23[2 * p]),                        \
                  "+l"(aA01[2 * p + 1]), "+l"(aA23[2 * p + 1]),                \
                  "+l"(aB01[2 * p + 1]), "+l"(aB23[2 * p + 1])                 \
                : "l"(xp.x), "l"(xp.y), "l"(wA.x), "l"(wA.y),                  \
                  "l"(wB.x), "l"(wB.y));                                       \
        }                                                                      \
    }

#define GEMM_ACC_DECL                                                          \
    unsigned long long aA01[8], aA23[8], aB01[8], aB23[8];                     \
    _Pragma("unroll") for (int b = 0; b < 8; ++b) {                            \
        aA01[b] = 0ull; aA23[b] = 0ull; aB01[b] = 0ull; aB23[b] = 0ull;        \
    }

#define GEMM_STORE(P, rowstride, n0)                                           \
    _Pragma("unroll") for (int b = 0; b < 8; ++b) {                            \
        ulonglong2 oA, oB;                                                     \
        oA.x = aA01[b]; oA.y = aA23[b];                                        \
        oB.x = aB01[b]; oB.y = aB23[b];                                        \
        float* dst = (P) + ((size_t)blockIdx.y * 8 + b) * (rowstride) + (n0);  \
        *(ulonglong2*)dst = oA;                                                \
        *(ulonglong2*)(dst + 4) = oB;                                          \
    }

// ------------------------- kernel 0: embed + rmsnorm(gamma1) ----------------
__global__ void embed_norm(const int* __restrict__ tokens,
                           const float* __restrict__ emb,
                           const float* __restrict__ gamma) {
    __shared__ float red[8];
    int b = blockIdx.x;
    int tok = tokens[b];
    const float* row = emb + (size_t)tok * DM;
    float loc[16];
    float sq = 0.f;
#pragma unroll
    for (int i = 0; i < 16; ++i) {
        float v = row[threadIdx.x + i * 256];
        loc[i] = v;
        sq += v * v;
    }
    int lane = threadIdx.x & 31, wid = threadIdx.x >> 5;
#pragma unroll
    for (int o = 16; o; o >>= 1) sq += __shfl_xor_sync(0xffffffffu, sq, o);
    if (!lane) red[wid] = sq;
    __syncthreads();
    float tot = 0.f;
#pragma unroll
    for (int w = 0; w < 8; ++w) tot += red[w];
    float rn = rsqrtf(tot * (1.0f / DM));
#pragma unroll
    for (int i = 0; i < 16; ++i) {
        int c = threadIdx.x + i * 256;
        g_h[b * DM + c] = loc[i];
        g_xn[b * DM + c] = loc[i] * rn * gamma[c];
    }
}

// ------------------------- generic split-K GEMM (M=8), 8 cols/thread --------
// XSEL: 0=g_xn, 1=g_attn, 2=g_g.  PSEL: 0=PA, 1=PB, 2=split (y<16->PA else PB)
template <int XSEL, int PSEL, int KCH>
__global__ __launch_bounds__(256, 2) void gemm8(const float* __restrict__ W,
                                                int K, int N) {
    const float* X = (XSEL == 0) ? g_xn : (XSEL == 1) ? g_attn : g_g;
    float* P;
    int py = blockIdx.y;
    if (PSEL == 0) P = g_PA;
    else if (PSEL == 1) P = g_PB;
    else { P = (blockIdx.y < 16) ? g_PA : g_PB; py = blockIdx.y & 15; }

    __shared__ __align__(16) unsigned long long xs[KCH][8];

    int k0 = blockIdx.y * KCH;
#pragma unroll
    for (int b = 0; b < 8; ++b)
        for (int kk = threadIdx.x; kk < KCH; kk += 256)
            xs[kk][b] = dup_f32(X[b * K + k0 + kk]);
    __syncthreads();

    int n0 = blockIdx.x * 2048 + threadIdx.x * 8;
    if (n0 >= N) return;

    GEMM_ACC_DECL;

    const float* wp = W + (size_t)k0 * N + n0;
#pragma unroll 8
    for (int kk = 0; kk < KCH; ++kk) GEMM_KSTEP8(wp, N);

#pragma unroll
    for (int b = 0; b < 8; ++b) {
        ulonglong2 oA, oB;
        oA.x = aA01[b]; oA.y = aA23[b];
        oB.x = aB01[b]; oB.y = aB23[b];
        float* dst = P + ((size_t)py * 8 + b) * N + n0;
        *(ulonglong2*)dst = oA;
        *(ulonglong2*)(dst + 4) = oB;
    }
}

// ------------------------- fused QKV GEMM (concat N=6144) -------------------
__global__ __launch_bounds__(256, 2) void gemm_qkv(const float* __restrict__ wq,
                                                   const float* __restrict__ wk,
                                                   const float* __restrict__ wv) {
    const int KCH = 64;
    __shared__ __align__(16) unsigned long long xs[KCH][8];
    const int K = DM;
    int k0 = blockIdx.y * KCH;
#pragma unroll
    for (int b = 0; b < 8; ++b)
        for (int kk = threadIdx.x; kk < KCH; kk += 256)
            xs[kk][b] = dup_f32(g_xn[b * K + k0 + kk]);
    __syncthreads();

    int nc = blockIdx.x * 2048 + threadIdx.x * 8;
    const float* W;
    int Nw, nl;
    if (nc < 4096)      { W = wq; Nw = 4096; nl = nc; }
    else if (nc < 5120) { W = wk; Nw = 1024; nl = nc - 4096; }
    else                { W = wv; Nw = 1024; nl = nc - 5120; }

    GEMM_ACC_DECL;

    const float* wp = W + (size_t)k0 * Nw + nl;
#pragma unroll 8
    for (int kk = 0; kk < KCH; ++kk) GEMM_KSTEP8(wp, Nw);

#pragma unroll
    for (int b = 0; b < 8; ++b) {
        ulonglong2 oA, oB;
        oA.x = aA01[b]; oA.y = aA23[b];
        oB.x = aB01[b]; oB.y = aB23[b];
        float* dst = g_PA + ((size_t)blockIdx.y * 8 + b) * 6144 + nc;
        *(ulonglong2*)dst = oA;
        *(ulonglong2*)(dst + 4) = oB;
    }
}

// ------------------------- fused w1|w3 GEMM (N=28672) -----------------------
__global__ __launch_bounds__(256, 2) void gemm_w13(const float* __restrict__ w1,
                                                   const float* __restrict__ w3) {
    const int KCH = 128;
    __shared__ __align__(16) unsigned long long xs[KCH][8];
    const int K = DM;
    int k0 = blockIdx.y * KCH;
#pragma unroll
    for (int b = 0; b < 8; ++b)
        for (int kk = threadIdx.x; kk < KCH; kk += 256)
            xs[kk][b] = dup_f32(g_xn[b * K + k0 + kk]);
    __syncthreads();

    int nc = blockIdx.x * 2048 + threadIdx.x * 8;
    const float* W;
    float* P;
    int nl;
    if (nc < HID) { W = w1; P = g_PA; nl = nc; }
    else          { W = w3; P = g_PB; nl = nc - HID; }

    GEMM_ACC_DECL;

    const float* wp = W + (size_t)k0 * HID + nl;
#pragma unroll 8
    for (int kk = 0; kk < KCH; ++kk) GEMM_KSTEP8(wp, HID);

#pragma unroll
    for (int b = 0; b < 8; ++b) {
        ulonglong2 oA, oB;
        oA.x = aA01[b]; oA.y = aA23[b];
        oB.x = aB01[b]; oB.y = aB23[b];
        float* dst = P + ((size_t)blockIdx.y * 8 + b) * HID + nl;
        *(ulonglong2*)dst = oA;
        *(ulonglong2*)(dst + 4) = oB;
    }
}

// --------------- QKV combine (sum 64 partials) + RoPE, float4 ---------------
__global__ void qkv_finish(const int* __restrict__ sp) {
    int p = blockIdx.x * 256 + threadIdx.x; // 12288 float4 slots
    int b = p / 1536;
    int r = p - b * 1536;
    int c0 = r * 4;
    float4 s = make_float4(0.f, 0.f, 0.f, 0.f);
#pragma unroll 8
    for (int ks = 0; ks < 64; ++ks) {
        float4 v = *(const float4*)(g_PA + ((size_t)ks * 8 + b) * 6144 + c0);
        s.x += v.x; s.y += v.y; s.z += v.z; s.w += v.w;
    }
    int pos = *sp;
    if (c0 < 5120) {
        int cc = (c0 < 4096) ? c0 : c0 - 4096;
        int i0 = (cc & 127) >> 1;
        float if0 = powf(10000.0f, -(float)i0 * (1.0f / 64.0f));
        float if1 = powf(10000.0f, -(float)(i0 + 1) * (1.0f / 64.0f));
        float sn0, cs0, sn1, cs1;
        sincosf((float)pos * if0, &sn0, &cs0);
        sincosf((float)pos * if1, &sn1, &cs1);
        float4 o;
        o.x = s.x * cs0 - s.y * sn0;
        o.y = s.x * sn0 + s.y * cs0;
        o.z = s.z * cs1 - s.w * sn1;
        o.w = s.z * sn1 + s.w * cs1;
        if (c0 < 4096)
            *(float4*)(g_xq + b * 4096 + c0) = o;
        else
            *(float4*)(g_xk + b * 1024 + (c0 - 4096)) = o;
    } else {
        *(float4*)(g_xv + b * 1024 + (c0 - 5120)) = s;
    }
}

// --------------- attention partial, 256 threads per (chunk, kv, b) -----------
__global__ __launch_bounds__(256) void attn_part(const float* __restrict__ ck,
                                                 const float* __restrict__ cv,
                                                 const int* __restrict__ sp) {
    int chunk = blockIdx.x, kv = blockIdx.y, b = blockIdx.z;
    int pos = *sp;
    int L = pos + 1;
    int s0 = chunk * ACH;
    int tid = threadIdx.x;
    int w = tid >> 5, l = tid & 31;

    __shared__ float4 qs[4][32];
    __shared__ float4 sc4[ACH];
    __shared__ float Mh[4], Lh[4];
    __shared__ float4 vred[8][4][32];

    if (tid < 128) {
        int h = tid >> 5, q = tid & 31;
        qs[h][q] = *(const float4*)(g_xq + (((b << 5) + (kv << 2) + h) << 7) + q * 4);
    }
    __syncthreads();

    const float scale = 0.08838834764831845f;
    const float4* kbase = (const float4*)(ck + ((size_t)b * MSEQ) * (NKV * HD) + kv * HD);

#pragma unroll 8
    for (int i = 0; i < ACH / 8; ++i) {
        int p = i * 8 + w;
        int s = s0 + p;
        float d0 = 0.f, d1 = 0.f, d2 = 0.f, d3 = 0.f;
        if (s < L) {
            float4 k4 = (s == pos)
                ? ((const float4*)(g_xk + (((b << 3) + kv) << 7)))[l]
                : kbase[(size_t)s * (NKV * HD / 4) + l];
            float4 qa = qs[0][l], qb = qs[1][l], qc = qs[2][l], qd = qs[3][l];
            d0 = k4.x * qa.x + k4.y * qa.y + k4.z * qa.z + k4.w * qa.w;
            d1 = k4.x * qb.x + k4.y * qb.y + k4.z * qb.z + k4.w * qb.w;
            d2 = k4.x * qc.x + k4.y * qc.y + k4.z * qc.z + k4.w * qc.w;
            d3 = k4.x * qd.x + k4.y * qd.y + k4.z * qd.z + k4.w * qd.w;
        }
#pragma unroll
        for (int o = 16; o; o >>= 1) {
            d0 += __shfl_xor_sync(0xffffffffu, d0, o);
            d1 += __shfl_xor_sync(0xffffffffu, d1, o);
            d2 += __shfl_xor_sync(0xffffffffu, d2, o);
            d3 += __shfl_xor_sync(0xffffffffu, d3, o);
        }
        if (l == 0) {
            bool valid = s < L;
            sc4[p] = valid ? make_float4(d0 * scale, d1 * scale, d2 * scale, d3 * scale)
                           : make_float4(-1e30f, -1e30f, -1e30f, -1e30f);
        }
    }
    __syncthreads();

    if (w < 4) {
        const float* scf = (const float*)sc4;
        float v0 = scf[l * 4 + w], v1 = scf[(l + 32) * 4 + w],
              v2 = scf[(l + 64) * 4 + w], v3 = scf[(l + 96) * 4 + w];
        float m = fmaxf(fmaxf(v0, v1), fmaxf(v2, v3));
#pragma unroll
        for (int o = 16; o; o >>= 1) m = fmaxf(m, __shfl_xor_sync(0xffffffffu, m, o));
        float p0 = expf(v0 - m), p1 = expf(v1 - m), p2 = expf(v2 - m), p3 = expf(v3 - m);
        float sum = p0 + p1 + p2 + p3;
#pragma unroll
        for (int o = 16; o; o >>= 1) sum += __shfl_xor_sync(0xffffffffu, sum, o);
        float* scw = (float*)sc4;
        scw[l * 4 + w] = p0;
        scw[(l + 32) * 4 + w] = p1;
        scw[(l + 64) * 4 + w] = p2;
        scw[(l + 96) * 4 + w] = p3;
        if (!l) { Mh[w] = m; Lh[w] = sum; }
    }
    __syncthreads();

    float4 a0 = make_float4(0.f, 0.f, 0.f, 0.f);
    float4 a1 = a0, a2 = a0, a3 = a0;
    int nc_ = pos - s0;
    if (nc_ > ACH) nc_ = ACH;
    if (nc_ < 0) nc_ = 0;
    const float4* vr = (const float4*)(cv + ((size_t)(b * MSEQ + s0)) * (NKV * HD) + kv * HD) + l;
#pragma unroll 8
    for (int ss = w; ss < nc_; ss += 8) {
        float4 v = vr[(size_t)ss * (NKV * HD / 4)];
        float4 p = sc4[ss];
        fma4(a0, p.x, v);
        fma4(a1, p.y, v);
        fma4(a2, p.z, v);
        fma4(a3, p.w, v);
    }
    int lp = pos - s0;
    if (lp >= 0 && lp < ACH && (lp & 7) == w) {
        float4 v = ((const float4*)(g_xv + (((b << 3) + kv) << 7)))[l];
        float4 p = sc4[lp];
        fma4(a0, p.x, v);
        fma4(a1, p.y, v);
        fma4(a2, p.z, v);
        fma4(a3, p.w, v);
    }
    vred[w][0][l] = a0;
    vred[w][1][l] = a1;
    vred[w][2][l] = a2;
    vred[w][3][l] = a3;
    __syncthreads();

    {
        int h = tid >> 6, j = tid & 63;
        float2 s2 = make_float2(0.f, 0.f);
#pragma unroll
        for (int ww = 0; ww < 8; ++ww) {
            float2 v = ((const float2*)vred[ww][h])[j];
            s2.x += v.x;
            s2.y += v.y;
        }
        int hg = (kv << 2) + h;
        *(float2*)(g_po + ((((size_t)(b << 5) + hg) << 4) + chunk) * HD + j * 2) = s2;
    }
    if (tid < 4) {
        int hg = (kv << 2) + tid;
        g_pm[(((b << 5) + hg) << 4) + chunk] = Mh[tid];
        g_pl[(((b << 5) + hg) << 4) + chunk] = Lh[tid];
    }
}

// --------------- attention: combine chunk partials ---------------------------
__global__ void attn_combine() {
    int h = blockIdx.x, b = blockIdx.y, d = threadIdx.x;
    int base = ((b << 5) + h) << 4;
    float M = -1e30f;
#pragma unroll
    for (int c = 0; c < NCHK; ++c) M = fmaxf(M, g_pm[base + c]);
    float Ls = 0.f, o = 0.f;
#pragma unroll
    for (int c = 0; c < NCHK; ++c) {
        float w = expf(g_pm[base + c] - M);
        Ls += g_pl[base + c] * w;
        o += g_po[(size_t)(base + c) * HD + d] * w;
    }
    g_attn[((b << 5) + h) * HD + d] = o / Ls;
}

// --------- fused: combine partials + residual + rmsnorm (one launch) --------
__global__ __launch_bounds__(1024) void fused_res_norm(const float* __restrict__ gamma,
                                                       int KS) {
    __shared__ float red[32];
    int b = blockIdx.x;
    int c = threadIdx.x * 4;
    float4 s = *(const float4*)(g_h + b * DM + c);
#pragma unroll 8
    for (int ks = 0; ks < KS; ++ks) {
        float4 v = *(const float4*)(g_PA + ((size_t)ks * 8 + b) * DM + c);
        s.x += v.x; s.y += v.y; s.z += v.z; s.w += v.w;
    }
    *(float4*)(g_h + b * DM + c) = s;
    float sq = s.x * s.x + s.y * s.y + s.z * s.z + s.w * s.w;
    int lane = threadIdx.x & 31, wid = threadIdx.x >> 5;
#pragma unroll
    for (int o = 16; o; o >>= 1) sq += __shfl_xor_sync(0xffffffffu, sq, o);
    if (!lane) red[wid] = sq;
    __syncthreads();
    if (threadIdx.x < 32) {
        float t = red[threadIdx.x];
#pragma unroll
        for (int o = 16; o; o >>= 1) t += __shfl_xor_sync(0xffffffffu, t, o);
        if (!threadIdx.x) red[0] = t;
    }
    __syncthreads();
    float rn = rsqrtf(red[0] * (1.0f / DM));
    float4 gm = *(const float4*)(gamma + c);
    float4 o;
    o.x = s.x * rn * gm.x;
    o.y = s.y * rn * gm.y;
    o.z = s.z * rn * gm.z;
    o.w = s.w * rn * gm.w;
    *(float4*)(g_xn + b * DM + c) = o;
}

// --------------- ffn gate: g = silu(x@w1) * (x@w3), float4 -------------------
__global__ void ffn_act(int KS) {
    int b = blockIdx.y;
    int c = (blockIdx.x * 256 + threadIdx.x) * 4;
    float4 s1 = make_float4(0.f, 0.f, 0.f, 0.f), s3 = s1;
#pragma unroll 8
    for (int ks = 0; ks < KS; ++ks) {
        float4 v1 = *(const float4*)(g_PA + ((size_t)ks * 8 + b) * HID + c);
        float4 v3 = *(const float4*)(g_PB + ((size_t)ks * 8 + b) * HID + c);
        s1.x += v1.x; s1.y += v1.y; s1.z += v1.z; s1.w += v1.w;
        s3.x += v3.x; s3.y += v3.y; s3.z += v3.z; s3.w += v3.w;
    }
    float4 o;
    o.x = s1.x / (1.0f + expf(-s1.x)) * s3.x;
    o.y = s1.y / (1.0f + expf(-s1.y)) * s3.y;
    o.z = s1.z / (1.0f + expf(-s1.z)) * s3.z;
    o.w = s1.w / (1.0f + expf(-s1.w)) * s3.w;
    *(float4*)(g_g + b * HID + c) = o;
}

// --------------- logits combine (16 PA + 16 PB partials), float4 -------------
__global__ void wout_finish(float* __restrict__ out) {
    int b = blockIdx.y;
    int c4 = blockIdx.x * 256 + threadIdx.x;
    if (c4 >= VOC / 4) return;
    int c = c4 * 4;
    float4 s = make_float4(0.f, 0.f, 0.f, 0.f);
#pragma unroll 4
    for (int ks = 0; ks < 16; ++ks) {
        float4 va = *(const float4*)(g_PA + ((size_t)ks * 8 + b) * VOC + c);
        float4 vb = *(const float4*)(g_PB + ((size_t)ks * 8 + b) * VOC + c);
        s.x += va.x + vb.x;
        s.y += va.y + vb.y;
        s.z += va.z + vb.z;
        s.w += va.w + vb.w;
    }
    *(float4*)(out + b * VOC + c) = s;
}

// ------------------------- launch --------------------------------------------
extern "C" void kernel_launch(void* const* d_in, const int* in_sizes, int n_in,
                              void* d_out, int out_size) {
    const int* tokens = (const int*)d_in[0];
    const int* sp = (const int*)d_in[1];
    const float* emb = (const float*)d_in[2];
    const float* g1 = (const float*)d_in[3];
    const float* g2 = (const float*)d_in[4];
    const float* gf = (const float*)d_in[5];
    const float* wq = (const float*)d_in[6];
    const float* wk = (const float*)d_in[7];
    const float* wv = (const float*)d_in[8];
    const float* wo = (const float*)d_in[9];
    const float* w1 = (const float*)d_in[10];
    const float* w2 = (const float*)d_in[11];
    const float* w3 = (const float*)d_in[12];
    const float* wout = (const float*)d_in[13];
    const float* ck = (const float*)d_in[14];
    const float* cv = (const float*)d_in[15];
    float* out = (float*)d_out;

    embed_norm<<<8, 256>>>(tokens, emb, g1);
    // QKV: 3 col-blocks x KS=64 (kchunk 64) = 192 blocks
    gemm_qkv<<<dim3(3, 64), 256>>>(wq, wk, wv);
    qkv_finish<<<48, 256>>>(sp);
    // attention: 16 chunks x 8 kv x 8 batch = 1024 blocks
    attn_part<<<dim3(NCHK, 8, 8), 256>>>(ck, cv, sp);
    attn_combine<<<dim3(32, 8), 128>>>();
    // wo: 2 col-blocks x KS=128 (kchunk 32) = 256 blocks
    gemm8<1, 0, 32><<<dim3(2, 128), 256>>>(wo, 4096, 4096);
    fused_res_norm<<<8, 1024>>>(g2, 128);
    // w1|w3 fused: 14 col-blocks x KS=32 (kchunk 128) = 448 blocks
    gemm_w13<<<dim3(14, 32), 256>>>(w1, w3);
    ffn_act<<<dim3(14, 8), 256>>>(32);
    // w2: 2 col-blocks x KS=128 (kchunk 112) = 256 blocks
    gemm8<2, 0, 112><<<dim3(2, 128), 256>>>(w2, 14336, 4096);
    fused_res_norm<<<8, 1024>>>(gf, 128);
    // w_out: 16 col-blocks x KS=32 (kchunk 128, PA|PB split) = 512 blocks
    gemm8<0, 2, 128><<<dim3(16, 32), 256>>>(wout, 4096, 32000);
    wout_finish<<<dim3(32, 8), 256>>>(out);
}

// round 6
// speedup vs baseline: 1.0241x; 1.0241x over previous
#include <cuda_runtime.h>
#include <cuda_bf16.h>
#include <math.h>

// ---------------------------------------------------------------------------
// Llama-style decode step, BATCH=8, S=1. R4 GEMM config (proven fastest):
// f32x2 FMA, 4 cols/thread, X staged once, exact smem, 3 blocks/SM.
// Attention: ACH=256 -> 512 blocks = single wave.
// ---------------------------------------------------------------------------

#define DM 4096
#define NH 32
#define NKV 8
#define HD 128
#define HID 14336
#define VOC 32000
#define MSEQ 2048
#define B8 8
#define ACH 256   // attention chunk length
#define NCHK 8    // MSEQ / ACH

// ------------------------- scratch (device globals) -------------------------
__device__ float g_h[B8 * DM];
__device__ float g_xn[B8 * DM];
__device__ float g_xq[B8 * NH * HD];
__device__ float g_xk[B8 * NKV * HD];
__device__ float g_xv[B8 * NKV * HD];
__device__ float g_pm[B8 * NH * NCHK];
__device__ float g_pl[B8 * NH * NCHK];
__device__ float g_po[B8 * NH * NCHK * HD];
__device__ float g_attn[B8 * DM];
__device__ float g_g[B8 * HID];
__device__ float g_PA[16 * 8 * 32000];
__device__ float g_PB[16 * 8 * 14336];

// ------------------------- helpers -------------------------
__device__ __forceinline__ void fma4(float4& a, float s, const float4& w) {
    a.x = fmaf(s, w.x, a.x);
    a.y = fmaf(s, w.y, a.y);
    a.z = fmaf(s, w.z, a.z);
    a.w = fmaf(s, w.w, a.w);
}

__device__ __forceinline__ unsigned long long dup_f32(float v) {
    unsigned long long pv;
    asm("mov.b64 %0, {%1, %1};" : "=l"(pv) : "f"(v));
    return pv;
}

// -------- GEMM inner macro: 1 LDG.128 + 4 LDS.128 + 16 FFMA2 per k ----------
#define GEMM_KSTEP(wp, stride)                                                 \
    {                                                                          \
        ulonglong2 w2 = __ldg((const ulonglong2*)(wp));                        \
        (wp) += (stride);                                                      \
        _Pragma("unroll") for (int p = 0; p < 4; ++p) {                        \
            ulonglong2 xp = *(const ulonglong2*)&xs[kk][2 * p];                \
            asm("fma.rn.f32x2 %0, %4, %6, %0;\n\t"                             \
                "fma.rn.f32x2 %1, %4, %7, %1;\n\t"                             \
                "fma.rn.f32x2 %2, %5, %6, %2;\n\t"                             \
                "fma.rn.f32x2 %3, %5, %7, %3;"                                 \
                : "+l"(a01[2 * p]), "+l"(a23[2 * p]),                          \
                  "+l"(a01[2 * p + 1]), "+l"(a23[2 * p + 1])                   \
                : "l"(xp.x), "l"(xp.y), "l"(w2.x), "l"(w2.y));                 \
        }                                                                      \
    }

// ------------------------- kernel 0: embed + rmsnorm(gamma1) ----------------
__global__ void embed_norm(const int* __restrict__ tokens,
                           const float* __restrict__ emb,
                           const float* __restrict__ gamma) {
    __shared__ float red[8];
    int b = blockIdx.x;
    int tok = tokens[b];
    const float* row = emb + (size_t)tok * DM;
    float loc[16];
    float sq = 0.f;
#pragma unroll
    for (int i = 0; i < 16; ++i) {
        float v = row[threadIdx.x + i * 256];
        loc[i] = v;
        sq += v * v;
    }
    int lane = threadIdx.x & 31, wid = threadIdx.x >> 5;
#pragma unroll
    for (int o = 16; o; o >>= 1) sq += __shfl_xor_sync(0xffffffffu, sq, o);
    if (!lane) red[wid] = sq;
    __syncthreads();
    float tot = 0.f;
#pragma unroll
    for (int w = 0; w < 8; ++w) tot += red[w];
    float rn = rsqrtf(tot * (1.0f / DM));
#pragma unroll
    for (int i = 0; i < 16; ++i) {
        int c = threadIdx.x + i * 256;
        g_h[b * DM + c] = loc[i];
        g_xn[b * DM + c] = loc[i] * rn * gamma[c];
    }
}

// ------------------------- generic split-K GEMM (M=8), f32x2 ----------------
// XSEL: 0 = g_xn, 1 = g_attn, 2 = g_g.  PSEL: 0 = g_PA, 1 = g_PB.
template <int XSEL, int PSEL, int KCH>
__global__ __launch_bounds__(256, 3) void gemm8(const float* __restrict__ W,
                                                int K, int N) {
    const float* X = (XSEL == 0) ? g_xn : (XSEL == 1) ? g_attn : g_g;
    float* P = (PSEL == 0) ? g_PA : g_PB;

    __shared__ __align__(16) unsigned long long xs[KCH][8];

    int k0 = blockIdx.y * KCH;
#pragma unroll
    for (int b = 0; b < 8; ++b)
        for (int kk = threadIdx.x; kk < KCH; kk += 256)
            xs[kk][b] = dup_f32(X[b * K + k0 + kk]);
    __syncthreads();

    int n0 = blockIdx.x * 1024 + threadIdx.x * 4;
    if (n0 >= N) return;

    unsigned long long a01[8], a23[8];
#pragma unroll
    for (int b = 0; b < 8; ++b) { a01[b] = 0ull; a23[b] = 0ull; }

    const float* wp = W + (size_t)k0 * N + n0;
#pragma unroll 8
    for (int kk = 0; kk < KCH; ++kk) GEMM_KSTEP(wp, N);

#pragma unroll
    for (int b = 0; b < 8; ++b) {
        ulonglong2 o;
        o.x = a01[b];
        o.y = a23[b];
        *(ulonglong2*)(P + ((size_t)blockIdx.y * 8 + b) * N + n0) = o;
    }
}

// ------------------------- fused QKV GEMM (concat N=6144) -------------------
__global__ __launch_bounds__(256, 3) void gemm_qkv(const float* __restrict__ wq,
                                                   const float* __restrict__ wk,
                                                   const float* __restrict__ wv) {
    const int KCH = 128;
    __shared__ __align__(16) unsigned long long xs[KCH][8];
    const int K = DM;
    int k0 = blockIdx.y * KCH;
#pragma unroll
    for (int b = 0; b < 8; ++b)
        for (int kk = threadIdx.x; kk < KCH; kk += 256)
            xs[kk][b] = dup_f32(g_xn[b * K + k0 + kk]);
    __syncthreads();

    int nc = blockIdx.x * 1024 + threadIdx.x * 4;
    const float* W;
    int Nw, nl;
    if (nc < 4096)      { W = wq; Nw = 4096; nl = nc; }
    else if (nc < 5120) { W = wk; Nw = 1024; nl = nc - 4096; }
    else                { W = wv; Nw = 1024; nl = nc - 5120; }

    unsigned long long a01[8], a23[8];
#pragma unroll
    for (int b = 0; b < 8; ++b) { a01[b] = 0ull; a23[b] = 0ull; }

    const float* wp = W + (size_t)k0 * Nw + nl;
#pragma unroll 8
    for (int kk = 0; kk < KCH; ++kk) GEMM_KSTEP(wp, Nw);

#pragma unroll
    for (int b = 0; b < 8; ++b) {
        ulonglong2 o;
        o.x = a01[b];
        o.y = a23[b];
        *(ulonglong2*)(g_PA + ((size_t)blockIdx.y * 8 + b) * 6144 + nc) = o;
    }
}

// ------------------------- fused w1|w3 GEMM (N=28672) -----------------------
__global__ __launch_bounds__(256, 3) void gemm_w13(const float* __restrict__ w1,
                                                   const float* __restrict__ w3) {
    const int KCH = 256;
    __shared__ __align__(16) unsigned long long xs[KCH][8];
    const int K = DM;
    int k0 = blockIdx.y * KCH;
#pragma unroll
    for (int b = 0; b < 8; ++b)
        for (int kk = threadIdx.x; kk < KCH; kk += 256)
            xs[kk][b] = dup_f32(g_xn[b * K + k0 + kk]);
    __syncthreads();

    int nc = blockIdx.x * 1024 + threadIdx.x * 4;
    const float* W;
    float* P;
    int nl;
    if (nc < HID) { W = w1; P = g_PA; nl = nc; }
    else          { W = w3; P = g_PB; nl = nc - HID; }

    unsigned long long a01[8], a23[8];
#pragma unroll
    for (int b = 0; b < 8; ++b) { a01[b] = 0ull; a23[b] = 0ull; }

    const float* wp = W + (size_t)k0 * HID + nl;
#pragma unroll 8
    for (int kk = 0; kk < KCH; ++kk) GEMM_KSTEP(wp, HID);

#pragma unroll
    for (int b = 0; b < 8; ++b) {
        ulonglong2 o;
        o.x = a01[b];
        o.y = a23[b];
        *(ulonglong2*)(P + ((size_t)blockIdx.y * 8 + b) * HID + nl) = o;
    }
}

// --------------- QKV combine (sum 32 partials) + RoPE, float4 ---------------
__global__ void qkv_finish(const int* __restrict__ sp) {
    int p = blockIdx.x * 256 + threadIdx.x; // 12288 float4 slots
    int b = p / 1536;
    int r = p - b * 1536;
    int c0 = r * 4;
    float4 s = make_float4(0.f, 0.f, 0.f, 0.f);
#pragma unroll 8
    for (int ks = 0; ks < 32; ++ks) {
        float4 v = *(const float4*)(g_PA + ((size_t)ks * 8 + b) * 6144 + c0);
        s.x += v.x; s.y += v.y; s.z += v.z; s.w += v.w;
    }
    int pos = *sp;
    if (c0 < 5120) {
        int cc = (c0 < 4096) ? c0 : c0 - 4096;
        int i0 = (cc & 127) >> 1;
        float if0 = powf(10000.0f, -(float)i0 * (1.0f / 64.0f));
        float if1 = powf(10000.0f, -(float)(i0 + 1) * (1.0f / 64.0f));
        float sn0, cs0, sn1, cs1;
        sincosf((float)pos * if0, &sn0, &cs0);
        sincosf((float)pos * if1, &sn1, &cs1);
        float4 o;
        o.x = s.x * cs0 - s.y * sn0;
        o.y = s.x * sn0 + s.y * cs0;
        o.z = s.z * cs1 - s.w * sn1;
        o.w = s.z * sn1 + s.w * cs1;
        if (c0 < 4096)
            *(float4*)(g_xq + b * 4096 + c0) = o;
        else
            *(float4*)(g_xk + b * 1024 + (c0 - 4096)) = o;
    } else {
        *(float4*)(g_xv + b * 1024 + (c0 - 5120)) = s;
    }
}

// --------------- attention partial, ACH=256, 256 thr, 512 blocks ------------
__global__ __launch_bounds__(256) void attn_part(const float* __restrict__ ck,
                                                 const float* __restrict__ cv,
                                                 const int* __restrict__ sp) {
    int chunk = blockIdx.x, kv = blockIdx.y, b = blockIdx.z;
    int pos = *sp;
    int L = pos + 1;
    int s0 = chunk * ACH;
    int tid = threadIdx.x;
    int w = tid >> 5, l = tid & 31;

    __shared__ float4 qs[4][32];
    __shared__ float4 sc4[ACH];       // (p0,p1,p2,p3) per position
    __shared__ float Mh[4], Lh[4];
    __shared__ float4 vred[8][4][32];

    if (tid < 128) {
        int h = tid >> 5, q = tid & 31;
        qs[h][q] = *(const float4*)(g_xq + (((b << 5) + (kv << 2) + h) << 7) + q * 4);
    }
    __syncthreads();

    const float scale = 0.08838834764831845f;
    const float4* kbase = (const float4*)(ck + ((size_t)b * MSEQ) * (NKV * HD) + kv * HD);

#pragma unroll 8
    for (int i = 0; i < ACH / 8; ++i) {
        int p = i * 8 + w;
        int s = s0 + p;
        float d0 = 0.f, d1 = 0.f, d2 = 0.f, d3 = 0.f;
        if (s < L) {
            float4 k4 = (s == pos)
                ? ((const float4*)(g_xk + (((b << 3) + kv) << 7)))[l]
                : kbase[(size_t)s * (NKV * HD / 4) + l];
            float4 qa = qs[0][l], qb = qs[1][l], qc = qs[2][l], qd = qs[3][l];
            d0 = k4.x * qa.x + k4.y * qa.y + k4.z * qa.z + k4.w * qa.w;
            d1 = k4.x * qb.x + k4.y * qb.y + k4.z * qb.z + k4.w * qb.w;
            d2 = k4.x * qc.x + k4.y * qc.y + k4.z * qc.z + k4.w * qc.w;
            d3 = k4.x * qd.x + k4.y * qd.y + k4.z * qd.z + k4.w * qd.w;
        }
#pragma unroll
        for (int o = 16; o; o >>= 1) {
            d0 += __shfl_xor_sync(0xffffffffu, d0, o);
            d1 += __shfl_xor_sync(0xffffffffu, d1, o);
            d2 += __shfl_xor_sync(0xffffffffu, d2, o);
            d3 += __shfl_xor_sync(0xffffffffu, d3, o);
        }
        if (l == 0) {
            bool valid = s < L;
            sc4[p] = valid ? make_float4(d0 * scale, d1 * scale, d2 * scale, d3 * scale)
                           : make_float4(-1e30f, -1e30f, -1e30f, -1e30f);
        }
    }
    __syncthreads();

    if (w < 4) { // warp w = head w softmax over 256 scores (component w)
        const float* scf = (const float*)sc4;
        float v[8];
#pragma unroll
        for (int j = 0; j < 8; ++j) v[j] = scf[(l + 32 * j) * 4 + w];
        float m = v[0];
#pragma unroll
        for (int j = 1; j < 8; ++j) m = fmaxf(m, v[j]);
#pragma unroll
        for (int o = 16; o; o >>= 1) m = fmaxf(m, __shfl_xor_sync(0xffffffffu, m, o));
        float pj[8];
        float sum = 0.f;
#pragma unroll
        for (int j = 0; j < 8; ++j) {
            pj[j] = expf(v[j] - m);
            sum += pj[j];
        }
#pragma unroll
        for (int o = 16; o; o >>= 1) sum += __shfl_xor_sync(0xffffffffu, sum, o);
        float* scw = (float*)sc4;
#pragma unroll
        for (int j = 0; j < 8; ++j) scw[(l + 32 * j) * 4 + w] = pj[j];
        if (!l) { Mh[w] = m; Lh[w] = sum; }
    }
    __syncthreads();

    // V pass: warp w covers positions w, w+8, ...
    float4 a0 = make_float4(0.f, 0.f, 0.f, 0.f);
    float4 a1 = a0, a2 = a0, a3 = a0;
    int nc_ = pos - s0;
    if (nc_ > ACH) nc_ = ACH;
    if (nc_ < 0) nc_ = 0;
    const float4* vr = (const float4*)(cv + ((size_t)(b * MSEQ + s0)) * (NKV * HD) + kv * HD) + l;
#pragma unroll 8
    for (int ss = w; ss < nc_; ss += 8) {
        float4 v = vr[(size_t)ss * (NKV * HD / 4)];
        float4 p = sc4[ss];
        fma4(a0, p.x, v);
        fma4(a1, p.y, v);
        fma4(a2, p.z, v);
        fma4(a3, p.w, v);
    }
    int lp = pos - s0;
    if (lp >= 0 && lp < ACH && (lp & 7) == w) {
        float4 v = ((const float4*)(g_xv + (((b << 3) + kv) << 7)))[l];
        float4 p = sc4[lp];
        fma4(a0, p.x, v);
        fma4(a1, p.y, v);
        fma4(a2, p.z, v);
        fma4(a3, p.w, v);
    }
    vred[w][0][l] = a0;
    vred[w][1][l] = a1;
    vred[w][2][l] = a2;
    vred[w][3][l] = a3;
    __syncthreads();

    {
        int h = tid >> 6, j = tid & 63;
        float2 s2 = make_float2(0.f, 0.f);
#pragma unroll
        for (int ww = 0; ww < 8; ++ww) {
            float2 v = ((const float2*)vred[ww][h])[j];
            s2.x += v.x;
            s2.y += v.y;
        }
        int hg = (kv << 2) + h;
        *(float2*)(g_po + ((((size_t)(b << 5) + hg) << 3) + chunk) * HD + j * 2) = s2;
    }
    if (tid < 4) {
        int hg = (kv << 2) + tid;
        g_pm[(((b << 5) + hg) << 3) + chunk] = Mh[tid];
        g_pl[(((b << 5) + hg) << 3) + chunk] = Lh[tid];
    }
}

// --------------- attention: combine chunk partials ---------------------------
__global__ void attn_combine() {
    int h = blockIdx.x, b = blockIdx.y, d = threadIdx.x; // 128 threads
    int base = ((b << 5) + h) << 3;
    float M = -1e30f;
#pragma unroll
    for (int c = 0; c < NCHK; ++c) M = fmaxf(M, g_pm[base + c]);
    float Ls = 0.f, o = 0.f;
#pragma unroll
    for (int c = 0; c < NCHK; ++c) {
        float w = expf(g_pm[base + c] - M);
        Ls += g_pl[base + c] * w;
        o += g_po[(size_t)(base + c) * HD + d] * w;
    }
    g_attn[((b << 5) + h) * HD + d] = o / Ls;
}

// --------- fused: combine partials + residual + rmsnorm (one launch) --------
__global__ __launch_bounds__(1024) void fused_res_norm(const float* __restrict__ gamma,
                                                       int KS) {
    __shared__ float red[32];
    int b = blockIdx.x;
    int c = threadIdx.x * 4;
    float4 s = *(const float4*)(g_h + b * DM + c);
#pragma unroll 8
    for (int ks = 0; ks < KS; ++ks) {
        float4 v = *(const float4*)(g_PA + ((size_t)ks * 8 + b) * DM + c);
        s.x += v.x; s.y += v.y; s.z += v.z; s.w += v.w;
    }
    *(float4*)(g_h + b * DM + c) = s;
    float sq = s.x * s.x + s.y * s.y + s.z * s.z + s.w * s.w;
    int lane = threadIdx.x & 31, wid = threadIdx.x >> 5;
#pragma unroll
    for (int o = 16; o; o >>= 1) sq += __shfl_xor_sync(0xffffffffu, sq, o);
    if (!lane) red[wid] = sq;
    __syncthreads();
    if (threadIdx.x < 32) {
        float t = red[threadIdx.x];
#pragma unroll
        for (int o = 16; o; o >>= 1) t += __shfl_xor_sync(0xffffffffu, t, o);
        if (!threadIdx.x) red[0] = t;
    }
    __syncthreads();
    float rn = rsqrtf(red[0] * (1.0f / DM));
    float4 gm = *(const float4*)(gamma + c);
    float4 o;
    o.x = s.x * rn * gm.x;
    o.y = s.y * rn * gm.y;
    o.z = s.z * rn * gm.z;
    o.w = s.w * rn * gm.w;
    *(float4*)(g_xn + b * DM + c) = o;
}

// --------------- ffn gate: g = silu(x@w1) * (x@w3), float4 -------------------
__global__ void ffn_act(int KS) {
    int b = blockIdx.y;
    int c = (blockIdx.x * 256 + threadIdx.x) * 4;
    float4 s1 = make_float4(0.f, 0.f, 0.f, 0.f), s3 = s1;
#pragma unroll 8
    for (int ks = 0; ks < KS; ++ks) {
        float4 v1 = *(const float4*)(g_PA + ((size_t)ks * 8 + b) * HID + c);
        float4 v3 = *(const float4*)(g_PB + ((size_t)ks * 8 + b) * HID + c);
        s1.x += v1.x; s1.y += v1.y; s1.z += v1.z; s1.w += v1.w;
        s3.x += v3.x; s3.y += v3.y; s3.z += v3.z; s3.w += v3.w;
    }
    float4 o;
    o.x = s1.x / (1.0f + expf(-s1.x)) * s3.x;
    o.y = s1.y / (1.0f + expf(-s1.y)) * s3.y;
    o.z = s1.z / (1.0f + expf(-s1.z)) * s3.z;
    o.w = s1.w / (1.0f + expf(-s1.w)) * s3.w;
    *(float4*)(g_g + b * HID + c) = o;
}

// --------------- logits combine, float4 --------------------------------------
__global__ void wout_finish(float* __restrict__ out, int KS) {
    int b = blockIdx.y;
    int c4 = blockIdx.x * 256 + threadIdx.x;
    if (c4 >= VOC / 4) return;
    int c = c4 * 4;
    float4 s = make_float4(0.f, 0.f, 0.f, 0.f);
#pragma unroll 4
    for (int ks = 0; ks < KS; ++ks) {
        float4 v = *(const float4*)(g_PA + ((size_t)ks * 8 + b) * VOC + c);
        s.x += v.x; s.y += v.y; s.z += v.z; s.w += v.w;
    }
    *(float4*)(out + b * VOC + c) = s;
}

// ------------------------- launch --------------------------------------------
extern "C" void kernel_launch(void* const* d_in, const int* in_sizes, int n_in,
                              void* d_out, int out_size) {
    const int* tokens = (const int*)d_in[0];
    const int* sp = (const int*)d_in[1];
    const float* emb = (const float*)d_in[2];
    const float* g1 = (const float*)d_in[3];
    const float* g2 = (const float*)d_in[4];
    const float* gf = (const float*)d_in[5];
    const float* wq = (const float*)d_in[6];
    const float* wk = (const float*)d_in[7];
    const float* wv = (const float*)d_in[8];
    const float* wo = (const float*)d_in[9];
    const float* w1 = (const float*)d_in[10];
    const float* w2 = (const float*)d_in[11];
    const float* w3 = (const float*)d_in[12];
    const float* wout = (const float*)d_in[13];
    const float* ck = (const float*)d_in[14];
    const float* cv = (const float*)d_in[15];
    float* out = (float*)d_out;

    embed_norm<<<8, 256>>>(tokens, emb, g1);
    // QKV: KS=32, kchunk=128 -> 192 blocks
    gemm_qkv<<<dim3(6, 32), 256>>>(wq, wk, wv);
    qkv_finish<<<48, 256>>>(sp);
    // attention: 8 chunks x 8 kv x 8 batch = 512 blocks (single wave)
    attn_part<<<dim3(NCHK, 8, 8), 256>>>(ck, cv, sp);
    attn_combine<<<dim3(32, 8), 128>>>();
    // wo: KS=64, kchunk=64 -> 256 blocks
    gemm8<1, 0, 64><<<dim3(4, 64), 256>>>(wo, 4096, 4096);
    fused_res_norm<<<8, 1024>>>(g2, 64);
    // w1|w3 fused: KS=16, kchunk=256 -> 448 blocks
    gemm_w13<<<dim3(28, 16), 256>>>(w1, w3);
    ffn_act<<<dim3(14, 8), 256>>>(16);
    // w2: KS=56, kchunk=256 -> 224 blocks (halved partial traffic vs R4)
    gemm8<2, 0, 256><<<dim3(4, 56), 256>>>(w2, 14336, 4096);
    fused_res_norm<<<8, 1024>>>(gf, 56);
    // w_out: KS=16, kchunk=256 -> 512 blocks
    gemm8<0, 0, 256><<<dim3(32, 16), 256>>>(wout, 4096, 32000);
    wout_finish<<<dim3(32, 8), 256>>>(out, 16);
}

// round 7
// speedup vs baseline: 1.0854x; 1.0599x over previous
#include <cuda_runtime.h>
#include <cuda_bf16.h>
#include <math.h>

// ---------------------------------------------------------------------------
// Llama-style decode step, BATCH=8, S=1. R4-proven GEMM config (f32x2 FMA,
// 4 cols/thread, X staged once, exact smem, 3 blocks/SM, evict-first weight
// loads) + flash-decode attention (ACH=256 single wave, ILP-4 score pass).
// ---------------------------------------------------------------------------

#define DM 4096
#define NH 32
#define NKV 8
#define HD 128
#define HID 14336
#define VOC 32000
#define MSEQ 2048
#define B8 8
#define ACH 256   // attention chunk length
#define NCHK 8    // MSEQ / ACH

// ------------------------- scratch (device globals) -------------------------
__device__ float g_h[B8 * DM];
__device__ float g_xn[B8 * DM];
__device__ float g_xq[B8 * NH * HD];
__device__ float g_xk[B8 * NKV * HD];
__device__ float g_xv[B8 * NKV * HD];
__device__ float g_pm[B8 * NH * NCHK];
__device__ float g_pl[B8 * NH * NCHK];
__device__ float g_po[B8 * NH * NCHK * HD];
__device__ float g_attn[B8 * DM];
__device__ float g_g[B8 * HID];
__device__ float g_PA[16 * 8 * 32000];
__device__ float g_PB[16 * 8 * 14336];

// ------------------------- helpers -------------------------
__device__ __forceinline__ void fma4(float4& a, float s, const float4& w) {
    a.x = fmaf(s, w.x, a.x);
    a.y = fmaf(s, w.y, a.y);
    a.z = fmaf(s, w.z, a.z);
    a.w = fmaf(s, w.w, a.w);
}

__device__ __forceinline__ unsigned long long dup_f32(float v) {
    unsigned long long pv;
    asm("mov.b64 %0, {%1, %1};" : "=l"(pv) : "f"(v));
    return pv;
}

// -------- GEMM inner macro: 1 LDG.128(.cs) + 4 LDS.128 + 16 FFMA2 per k -----
#define GEMM_KSTEP(wp, stride)                                                 \
    {                                                                          \
        ulonglong2 w2;                                                         \
        asm("ld.global.cs.v2.u64 {%0,%1}, [%2];"                               \
            : "=l"(w2.x), "=l"(w2.y) : "l"(wp));                               \
        (wp) += (stride);                                                      \
        _Pragma("unroll") for (int p = 0; p < 4; ++p) {                        \
            ulonglong2 xp = *(const ulonglong2*)&xs[kk][2 * p];                \
            asm("fma.rn.f32x2 %0, %4, %6, %0;\n\t"                             \
                "fma.rn.f32x2 %1, %4, %7, %1;\n\t"                             \
                "fma.rn.f32x2 %2, %5, %6, %2;\n\t"                             \
                "fma.rn.f32x2 %3, %5, %7, %3;"                                 \
                : "+l"(a01[2 * p]), "+l"(a23[2 * p]),                          \
                  "+l"(a01[2 * p + 1]), "+l"(a23[2 * p + 1])                   \
                : "l"(xp.x), "l"(xp.y), "l"(w2.x), "l"(w2.y));                 \
        }                                                                      \
    }

// ------------------------- kernel 0: embed + rmsnorm(gamma1) ----------------
__global__ void embed_norm(const int* __restrict__ tokens,
                           const float* __restrict__ emb,
                           const float* __restrict__ gamma) {
    __shared__ float red[8];
    int b = blockIdx.x;
    int tok = tokens[b];
    const float* row = emb + (size_t)tok * DM;
    float loc[16];
    float sq = 0.f;
#pragma unroll
    for (int i = 0; i < 16; ++i) {
        float v = row[threadIdx.x + i * 256];
        loc[i] = v;
        sq += v * v;
    }
    int lane = threadIdx.x & 31, wid = threadIdx.x >> 5;
#pragma unroll
    for (int o = 16; o; o >>= 1) sq += __shfl_xor_sync(0xffffffffu, sq, o);
    if (!lane) red[wid] = sq;
    __syncthreads();
    float tot = 0.f;
#pragma unroll
    for (int w = 0; w < 8; ++w) tot += red[w];
    float rn = rsqrtf(tot * (1.0f / DM));
#pragma unroll
    for (int i = 0; i < 16; ++i) {
        int c = threadIdx.x + i * 256;
        g_h[b * DM + c] = loc[i];
        g_xn[b * DM + c] = loc[i] * rn * gamma[c];
    }
}

// ------------------------- generic split-K GEMM (M=8), f32x2 ----------------
// XSEL: 0 = g_xn, 1 = g_attn, 2 = g_g.  PSEL: 0 = g_PA, 1 = g_PB.
template <int XSEL, int PSEL, int KCH>
__global__ __launch_bounds__(256, 3) void gemm8(const float* __restrict__ W,
                                                int K, int N) {
    const float* X = (XSEL == 0) ? g_xn : (XSEL == 1) ? g_attn : g_g;
    float* P = (PSEL == 0) ? g_PA : g_PB;

    __shared__ __align__(16) unsigned long long xs[KCH][8];

    int k0 = blockIdx.y * KCH;
#pragma unroll
    for (int b = 0; b < 8; ++b)
        for (int kk = threadIdx.x; kk < KCH; kk += 256)
            xs[kk][b] = dup_f32(X[b * K + k0 + kk]);
    __syncthreads();

    int n0 = blockIdx.x * 1024 + threadIdx.x * 4;
    if (n0 >= N) return;

    unsigned long long a01[8], a23[8];
#pragma unroll
    for (int b = 0; b < 8; ++b) { a01[b] = 0ull; a23[b] = 0ull; }

    const float* wp = W + (size_t)k0 * N + n0;
#pragma unroll 8
    for (int kk = 0; kk < KCH; ++kk) GEMM_KSTEP(wp, N);

#pragma unroll
    for (int b = 0; b < 8; ++b) {
        ulonglong2 o;
        o.x = a01[b];
        o.y = a23[b];
        *(ulonglong2*)(P + ((size_t)blockIdx.y * 8 + b) * N + n0) = o;
    }
}

// ------------------------- fused QKV GEMM (concat N=6144) -------------------
__global__ __launch_bounds__(256, 3) void gemm_qkv(const float* __restrict__ wq,
                                                   const float* __restrict__ wk,
                                                   const float* __restrict__ wv) {
    const int KCH = 128;
    __shared__ __align__(16) unsigned long long xs[KCH][8];
    const int K = DM;
    int k0 = blockIdx.y * KCH;
#pragma unroll
    for (int b = 0; b < 8; ++b)
        for (int kk = threadIdx.x; kk < KCH; kk += 256)
            xs[kk][b] = dup_f32(g_xn[b * K + k0 + kk]);
    __syncthreads();

    int nc = blockIdx.x * 1024 + threadIdx.x * 4;
    const float* W;
    int Nw, nl;
    if (nc < 4096)      { W = wq; Nw = 4096; nl = nc; }
    else if (nc < 5120) { W = wk; Nw = 1024; nl = nc - 4096; }
    else                { W = wv; Nw = 1024; nl = nc - 5120; }

    unsigned long long a01[8], a23[8];
#pragma unroll
    for (int b = 0; b < 8; ++b) { a01[b] = 0ull; a23[b] = 0ull; }

    const float* wp = W + (size_t)k0 * Nw + nl;
#pragma unroll 8
    for (int kk = 0; kk < KCH; ++kk) GEMM_KSTEP(wp, Nw);

#pragma unroll
    for (int b = 0; b < 8; ++b) {
        ulonglong2 o;
        o.x = a01[b];
        o.y = a23[b];
        *(ulonglong2*)(g_PA + ((size_t)blockIdx.y * 8 + b) * 6144 + nc) = o;
    }
}

// ------------------------- fused w1|w3 GEMM (N=28672) -----------------------
__global__ __launch_bounds__(256, 3) void gemm_w13(const float* __restrict__ w1,
                                                   const float* __restrict__ w3) {
    const int KCH = 256;
    __shared__ __align__(16) unsigned long long xs[KCH][8];
    const int K = DM;
    int k0 = blockIdx.y * KCH;
#pragma unroll
    for (int b = 0; b < 8; ++b)
        for (int kk = threadIdx.x; kk < KCH; kk += 256)
            xs[kk][b] = dup_f32(g_xn[b * K + k0 + kk]);
    __syncthreads();

    int nc = blockIdx.x * 1024 + threadIdx.x * 4;
    const float* W;
    float* P;
    int nl;
    if (nc < HID) { W = w1; P = g_PA; nl = nc; }
    else          { W = w3; P = g_PB; nl = nc - HID; }

    unsigned long long a01[8], a23[8];
#pragma unroll
    for (int b = 0; b < 8; ++b) { a01[b] = 0ull; a23[b] = 0ull; }

    const float* wp = W + (size_t)k0 * HID + nl;
#pragma unroll 8
    for (int kk = 0; kk < KCH; ++kk) GEMM_KSTEP(wp, HID);

#pragma unroll
    for (int b = 0; b < 8; ++b) {
        ulonglong2 o;
        o.x = a01[b];
        o.y = a23[b];
        *(ulonglong2*)(P + ((size_t)blockIdx.y * 8 + b) * HID + nl) = o;
    }
}

// --------------- QKV combine (sum 32 partials) + RoPE, float4 ---------------
__global__ void qkv_finish(const int* __restrict__ sp) {
    int p = blockIdx.x * 256 + threadIdx.x; // 12288 float4 slots
    int b = p / 1536;
    int r = p - b * 1536;
    int c0 = r * 4;
    float4 s = make_float4(0.f, 0.f, 0.f, 0.f);
#pragma unroll 8
    for (int ks = 0; ks < 32; ++ks) {
        float4 v = *(const float4*)(g_PA + ((size_t)ks * 8 + b) * 6144 + c0);
        s.x += v.x; s.y += v.y; s.z += v.z; s.w += v.w;
    }
    int pos = *sp;
    if (c0 < 5120) {
        int cc = (c0 < 4096) ? c0 : c0 - 4096;
        int i0 = (cc & 127) >> 1;
        float if0 = powf(10000.0f, -(float)i0 * (1.0f / 64.0f));
        float if1 = powf(10000.0f, -(float)(i0 + 1) * (1.0f / 64.0f));
        float sn0, cs0, sn1, cs1;
        sincosf((float)pos * if0, &sn0, &cs0);
        sincosf((float)pos * if1, &sn1, &cs1);
        float4 o;
        o.x = s.x * cs0 - s.y * sn0;
        o.y = s.x * sn0 + s.y * cs0;
        o.z = s.z * cs1 - s.w * sn1;
        o.w = s.z * sn1 + s.w * cs1;
        if (c0 < 4096)
            *(float4*)(g_xq + b * 4096 + c0) = o;
        else
            *(float4*)(g_xk + b * 1024 + (c0 - 4096)) = o;
    } else {
        *(float4*)(g_xv + b * 1024 + (c0 - 5120)) = s;
    }
}

// --------------- attention partial, ACH=256, 256 thr, 512 blocks ------------
// Score pass: 4 positions per warp-iteration (4 indep LDG + 16 indep shfl
// chains); Q held in registers (loop-invariant).
__global__ __launch_bounds__(256) void attn_part(const float* __restrict__ ck,
                                                 const float* __restrict__ cv,
                                                 const int* __restrict__ sp) {
    int chunk = blockIdx.x, kv = blockIdx.y, b = blockIdx.z;
    int pos = *sp;
    int L = pos + 1;
    int s0 = chunk * ACH;
    int tid = threadIdx.x;
    int w = tid >> 5, l = tid & 31;

    __shared__ float4 qs[4][32];
    __shared__ float4 sc4[ACH];       // (p0,p1,p2,p3) per position
    __shared__ float Mh[4], Lh[4];
    __shared__ float4 vred[8][4][32];

    if (tid < 128) {
        int h = tid >> 5, q = tid & 31;
        qs[h][q] = *(const float4*)(g_xq + (((b << 5) + (kv << 2) + h) << 7) + q * 4);
    }
    __syncthreads();

    const float scale = 0.08838834764831845f;
    const float4* kbase = (const float4*)(ck + ((size_t)b * MSEQ) * (NKV * HD) + kv * HD);
    const float4* xkrow = (const float4*)(g_xk + (((b << 3) + kv) << 7));

    float4 qv0 = qs[0][l], qv1 = qs[1][l], qv2 = qs[2][l], qv3 = qs[3][l];

#pragma unroll
    for (int i = 0; i < ACH / 32; ++i) {
        int p0 = i * 32 + w;
        float4 k4[4];
#pragma unroll
        for (int j = 0; j < 4; ++j) {
            int s = s0 + p0 + j * 8;
            const float4* kr = (s == pos) ? xkrow : (kbase + (size_t)s * (NKV * HD / 4));
            k4[j] = (s < L) ? kr[l] : make_float4(0.f, 0.f, 0.f, 0.f);
        }
        float d[4][4];
#pragma unroll
        for (int j = 0; j < 4; ++j) {
            d[j][0] = k4[j].x * qv0.x + k4[j].y * qv0.y + k4[j].z * qv0.z + k4[j].w * qv0.w;
            d[j][1] = k4[j].x * qv1.x + k4[j].y * qv1.y + k4[j].z * qv1.z + k4[j].w * qv1.w;
            d[j][2] = k4[j].x * qv2.x + k4[j].y * qv2.y + k4[j].z * qv2.z + k4[j].w * qv2.w;
            d[j][3] = k4[j].x * qv3.x + k4[j].y * qv3.y + k4[j].z * qv3.z + k4[j].w * qv3.w;
        }
#pragma unroll
        for (int o = 16; o; o >>= 1) {
#pragma unroll
            for (int j = 0; j < 4; ++j) {
                d[j][0] += __shfl_xor_sync(0xffffffffu, d[j][0], o);
                d[j][1] += __shfl_xor_sync(0xffffffffu, d[j][1], o);
                d[j][2] += __shfl_xor_sync(0xffffffffu, d[j][2], o);
                d[j][3] += __shfl_xor_sync(0xffffffffu, d[j][3], o);
            }
        }
        if (l == 0) {
#pragma unroll
            for (int j = 0; j < 4; ++j) {
                int s = s0 + p0 + j * 8;
                sc4[p0 + j * 8] = (s < L)
                    ? make_float4(d[j][0] * scale, d[j][1] * scale,
                                  d[j][2] * scale, d[j][3] * scale)
                    : make_float4(-1e30f, -1e30f, -1e30f, -1e30f);
            }
        }
    }
    __syncthreads();

    if (w < 4) { // warp w = head w softmax over 256 scores (component w)
        const float* scf = (const float*)sc4;
        float v[8];
#pragma unroll
        for (int j = 0; j < 8; ++j) v[j] = scf[(l + 32 * j) * 4 + w];
        float m = v[0];
#pragma unroll
        for (int j = 1; j < 8; ++j) m = fmaxf(m, v[j]);
#pragma unroll
        for (int o = 16; o; o >>= 1) m = fmaxf(m, __shfl_xor_sync(0xffffffffu, m, o));
        float pj[8];
        float sum = 0.f;
#pragma unroll
        for (int j = 0; j < 8; ++j) {
            pj[j] = expf(v[j] - m);
            sum += pj[j];
        }
#pragma unroll
        for (int o = 16; o; o >>= 1) sum += __shfl_xor_sync(0xffffffffu, sum, o);
        float* scw = (float*)sc4;
#pragma unroll
        for (int j = 0; j < 8; ++j) scw[(l + 32 * j) * 4 + w] = pj[j];
        if (!l) { Mh[w] = m; Lh[w] = sum; }
    }
    __syncthreads();

    // V pass: warp w covers positions w, w+8, ...
    float4 a0 = make_float4(0.f, 0.f, 0.f, 0.f);
    float4 a1 = a0, a2 = a0, a3 = a0;
    int nc_ = pos - s0;
    if (nc_ > ACH) nc_ = ACH;
    if (nc_ < 0) nc_ = 0;
    const float4* vr = (const float4*)(cv + ((size_t)(b * MSEQ + s0)) * (NKV * HD) + kv * HD) + l;
#pragma unroll 8
    for (int ss = w; ss < nc_; ss += 8) {
        float4 v = vr[(size_t)ss * (NKV * HD / 4)];
        float4 p = sc4[ss];
        fma4(a0, p.x, v);
        fma4(a1, p.y, v);
        fma4(a2, p.z, v);
        fma4(a3, p.w, v);
    }
    int lp = pos - s0;
    if (lp >= 0 && lp < ACH && (lp & 7) == w) {
        float4 v = ((const float4*)(g_xv + (((b << 3) + kv) << 7)))[l];
        float4 p = sc4[lp];
        fma4(a0, p.x, v);
        fma4(a1, p.y, v);
        fma4(a2, p.z, v);
        fma4(a3, p.w, v);
    }
    vred[w][0][l] = a0;
    vred[w][1][l] = a1;
    vred[w][2][l] = a2;
    vred[w][3][l] = a3;
    __syncthreads();

    {
        int h = tid >> 6, j = tid & 63;
        float2 s2 = make_float2(0.f, 0.f);
#pragma unroll
        for (int ww = 0; ww < 8; ++ww) {
            float2 v = ((const float2*)vred[ww][h])[j];
            s2.x += v.x;
            s2.y += v.y;
        }
        int hg = (kv << 2) + h;
        *(float2*)(g_po + ((((size_t)(b << 5) + hg) << 3) + chunk) * HD + j * 2) = s2;
    }
    if (tid < 4) {
        int hg = (kv << 2) + tid;
        g_pm[(((b << 5) + hg) << 3) + chunk] = Mh[tid];
        g_pl[(((b << 5) + hg) << 3) + chunk] = Lh[tid];
    }
}

// --------------- attention: combine chunk partials ---------------------------
__global__ void attn_combine() {
    int h = blockIdx.x, b = blockIdx.y, d = threadIdx.x; // 128 threads
    int base = ((b << 5) + h) << 3;
    float M = -1e30f;
#pragma unroll
    for (int c = 0; c < NCHK; ++c) M = fmaxf(M, g_pm[base + c]);
    float Ls = 0.f, o = 0.f;
#pragma unroll
    for (int c = 0; c < NCHK; ++c) {
        float w = expf(g_pm[base + c] - M);
        Ls += g_pl[base + c] * w;
        o += g_po[(size_t)(base + c) * HD + d] * w;
    }
    g_attn[((b << 5) + h) * HD + d] = o / Ls;
}

// --------- fused: combine partials + residual + rmsnorm (one launch) --------
__global__ __launch_bounds__(1024) void fused_res_norm(const float* __restrict__ gamma,
                                                       int KS) {
    __shared__ float red[32];
    int b = blockIdx.x;
    int c = threadIdx.x * 4;
    float4 s = *(const float4*)(g_h + b * DM + c);
#pragma unroll 8
    for (int ks = 0; ks < KS; ++ks) {
        float4 v = *(const float4*)(g_PA + ((size_t)ks * 8 + b) * DM + c);
        s.x += v.x; s.y += v.y; s.z += v.z; s.w += v.w;
    }
    *(float4*)(g_h + b * DM + c) = s;
    float sq = s.x * s.x + s.y * s.y + s.z * s.z + s.w * s.w;
    int lane = threadIdx.x & 31, wid = threadIdx.x >> 5;
#pragma unroll
    for (int o = 16; o; o >>= 1) sq += __shfl_xor_sync(0xffffffffu, sq, o);
    if (!lane) red[wid] = sq;
    __syncthreads();
    if (threadIdx.x < 32) {
        float t = red[threadIdx.x];
#pragma unroll
        for (int o = 16; o; o >>= 1) t += __shfl_xor_sync(0xffffffffu, t, o);
        if (!threadIdx.x) red[0] = t;
    }
    __syncthreads();
    float rn = rsqrtf(red[0] * (1.0f / DM));
    float4 gm = *(const float4*)(gamma + c);
    float4 o;
    o.x = s.x * rn * gm.x;
    o.y = s.y * rn * gm.y;
    o.z = s.z * rn * gm.z;
    o.w = s.w * rn * gm.w;
    *(float4*)(g_xn + b * DM + c) = o;
}

// --------------- ffn gate: g = silu(x@w1) * (x@w3), float4 -------------------
__global__ void ffn_act(int KS) {
    int b = blockIdx.y;
    int c = (blockIdx.x * 256 + threadIdx.x) * 4;
    float4 s1 = make_float4(0.f, 0.f, 0.f, 0.f), s3 = s1;
#pragma unroll 8
    for (int ks = 0; ks < KS; ++ks) {
        float4 v1 = *(const float4*)(g_PA + ((size_t)ks * 8 + b) * HID + c);
        float4 v3 = *(const float4*)(g_PB + ((size_t)ks * 8 + b) * HID + c);
        s1.x += v1.x; s1.y += v1.y; s1.z += v1.z; s1.w += v1.w;
        s3.x += v3.x; s3.y += v3.y; s3.z += v3.z; s3.w += v3.w;
    }
    float4 o;
    o.x = s1.x / (1.0f + expf(-s1.x)) * s3.x;
    o.y = s1.y / (1.0f + expf(-s1.y)) * s3.y;
    o.z = s1.z / (1.0f + expf(-s1.z)) * s3.z;
    o.w = s1.w / (1.0f + expf(-s1.w)) * s3.w;
    *(float4*)(g_g + b * HID + c) = o;
}

// --------------- logits combine, float4 --------------------------------------
__global__ void wout_finish(float* __restrict__ out, int KS) {
    int b = blockIdx.y;
    int c4 = blockIdx.x * 256 + threadIdx.x;
    if (c4 >= VOC / 4) return;
    int c = c4 * 4;
    float4 s = make_float4(0.f, 0.f, 0.f, 0.f);
#pragma unroll 4
    for (int ks = 0; ks < KS; ++ks) {
        float4 v = *(const float4*)(g_PA + ((size_t)ks * 8 + b) * VOC + c);
        s.x += v.x; s.y += v.y; s.z += v.z; s.w += v.w;
    }
    *(float4*)(out + b * VOC + c) = s;
}

// ------------------------- launch --------------------------------------------
extern "C" void kernel_launch(void* const* d_in, const int* in_sizes, int n_in,
                              void* d_out, int out_size) {
    const int* tokens = (const int*)d_in[0];
    const int* sp = (const int*)d_in[1];
    const float* emb = (const float*)d_in[2];
    const float* g1 = (const float*)d_in[3];
    const float* g2 = (const float*)d_in[4];
    const float* gf = (const float*)d_in[5];
    const float* wq = (const float*)d_in[6];
    const float* wk = (const float*)d_in[7];
    const float* wv = (const float*)d_in[8];
    const float* wo = (const float*)d_in[9];
    const float* w1 = (const float*)d_in[10];
    const float* w2 = (const float*)d_in[11];
    const float* w3 = (const float*)d_in[12];
    const float* wout = (const float*)d_in[13];
    const float* ck = (const float*)d_in[14];
    const float* cv = (const float*)d_in[15];
    float* out = (float*)d_out;

    embed_norm<<<8, 256>>>(tokens, emb, g1);
    // QKV: KS=32, kchunk=128 -> 192 blocks
    gemm_qkv<<<dim3(6, 32), 256>>>(wq, wk, wv);
    qkv_finish<<<48, 256>>>(sp);
    // attention: 8 chunks x 8 kv x 8 batch = 512 blocks (single wave)
    attn_part<<<dim3(NCHK, 8, 8), 256>>>(ck, cv, sp);
    attn_combine<<<dim3(32, 8), 128>>>();
    // wo: KS=64, kchunk=64 -> 256 blocks
    gemm8<1, 0, 64><<<dim3(4, 64), 256>>>(wo, 4096, 4096);
    fused_res_norm<<<8, 1024>>>(g2, 64);
    // w1|w3 fused: KS=16, kchunk=256 -> 448 blocks
    gemm_w13<<<dim3(28, 16), 256>>>(w1, w3);
    ffn_act<<<dim3(14, 8), 256>>>(16);
    // w2: KS=112, kchunk=128 -> 448 blocks (R4-proven config)
    gemm8<2, 0, 128><<<dim3(4, 112), 256>>>(w2, 14336, 4096);
    fused_res_norm<<<8, 1024>>>(gf, 112);
    // w_out: KS=16, kchunk=256 -> 512 blocks
    gemm8<0, 0, 256><<<dim3(32, 16), 256>>>(wout, 4096, 32000);
    wout_finish<<<dim3(32, 8), 256>>>(out, 16);
}